// round 6
// baseline (speedup 1.0000x reference)
#include <cuda_runtime.h>
#include <stdint.h>

#define B 64
#define T 512
#define D 384
#define MAX_LEN 4096
#define D4 (D / 4)          // 96 float4 per row
#define ROWS_PER_WARP 4

// scratch: source frame index per output position, -1 = masked (write zeros)
__device__ int g_idx[B * MAX_LEN];

// ---------------------------------------------------------------------------
// Kernel A: per-batch cumsum via shuffle warp-scans (2 barriers total),
// scatter frame index, tail fill, mel_len write.
// One block per batch, 512 threads (16 warps).
// ---------------------------------------------------------------------------
__global__ void lr_scan_scatter(const int* __restrict__ duration,
                                float* __restrict__ out_tail /* mel_len as f32 */)
{
    __shared__ int s_part[16];
    const int b    = blockIdx.x;
    const int t    = threadIdx.x;
    const int wid  = t >> 5;
    const int lane = t & 31;

    const int v = duration[b * T + t];

    // intra-warp inclusive scan
    int inc = v;
    #pragma unroll
    for (int off = 1; off < 32; off <<= 1) {
        int n = __shfl_up_sync(0xffffffffu, inc, off);
        if (lane >= off) inc += n;
    }
    if (lane == 31) s_part[wid] = inc;
    __syncthreads();

    // warp 0 scans the 16 warp totals (inclusive)
    if (wid == 0 && lane < 16) {
        int p = s_part[lane];
        #pragma unroll
        for (int off = 1; off < 16; off <<= 1) {
            int n = __shfl_up_sync(0x0000ffffu, p, off);
            if (lane >= off) p += n;
        }
        s_part[lane] = p;
    }
    __syncthreads();

    const int base  = (wid > 0) ? s_part[wid - 1] : 0;
    const int end   = base + inc;
    const int start = end - v;
    const int mel   = s_part[15];

    int* idx_b = g_idx + b * MAX_LEN;
    for (int p = start; p < end; ++p) idx_b[p] = t;           // <= 7 iters
    for (int p = mel + t; p < MAX_LEN; p += T) idx_b[p] = -1; // masked tail

    if (t == 0) out_tail[b] = (float)mel;
}

// ---------------------------------------------------------------------------
// Kernel B: warp-per-row gather, 4 rows per warp.
// Lanes cover d4 = {lane, lane+32, lane+64}. idx is warp-uniform, so the
// masked-row branch is divergence-free: zero rows issue NO x loads.
// rows = B*MAX_LEN = 262144; warps = 65536; blocks(256) = 8192 (exact).
// ---------------------------------------------------------------------------
__global__ void lr_gather(const float4* __restrict__ x,   // [B, T, D4]
                          float4* __restrict__ out)        // [B, MAX_LEN, D4]
{
    const int warp = (blockIdx.x * blockDim.x + threadIdx.x) >> 5;
    const int lane = threadIdx.x & 31;
    const int row0 = warp * ROWS_PER_WARP;    // row = b*MAX_LEN + p

    const float4 z = make_float4(0.f, 0.f, 0.f, 0.f);
    float4 v[ROWS_PER_WARP][3];
    int    idxr[ROWS_PER_WARP];

    // batch the (broadcast) index loads first
    #pragma unroll
    for (int r = 0; r < ROWS_PER_WARP; ++r)
        idxr[r] = __ldg(&g_idx[row0 + r]);

    // issue x loads only for live rows (warp-uniform predicate)
    #pragma unroll
    for (int r = 0; r < ROWS_PER_WARP; ++r) {
        const int bp = row0 + r;
        const int bb = bp >> 12;              // / MAX_LEN
        if (idxr[r] >= 0) {
            const float4* src = x + ((long long)bb * T + idxr[r]) * D4;
            v[r][0] = __ldg(src + lane);
            v[r][1] = __ldg(src + lane + 32);
            v[r][2] = __ldg(src + lane + 64);
        } else {
            v[r][0] = z; v[r][1] = z; v[r][2] = z;
        }
    }

    #pragma unroll
    for (int r = 0; r < ROWS_PER_WARP; ++r) {
        float4* dst = out + (long long)(row0 + r) * D4;
        __stcs(dst + lane,      v[r][0]);
        __stcs(dst + lane + 32, v[r][1]);
        __stcs(dst + lane + 64, v[r][2]);
    }
}

extern "C" void kernel_launch(void* const* d_in, const int* in_sizes, int n_in,
                              void* d_out, int out_size)
{
    const float* x        = (const float*)d_in[0];
    const int*   duration = (const int*)d_in[1];

    float* out = (float*)d_out;
    float* out_tail = out + (size_t)B * MAX_LEN * D;   // mel_len region (64 floats)

    lr_scan_scatter<<<B, T>>>(duration, out_tail);

    const int total_warps = (B * MAX_LEN) / ROWS_PER_WARP;   // 65536
    const int threads = 256;
    const int blocks  = total_warps * 32 / threads;          // 8192
    lr_gather<<<blocks, threads>>>((const float4*)x, (float4*)out);
}

// round 7
// speedup vs baseline: 1.2270x; 1.2270x over previous
#include <cuda_runtime.h>
#include <stdint.h>

#define B 64
#define T 512
#define D 384
#define MAX_LEN 4096
#define D4 (D / 4)          // 96 float4 per row
#define ROWS_PER_WARP 4

// scratch: source frame index per output position (valid only for p < mel)
__device__ int g_idx[B * MAX_LEN];
__device__ int g_mel[B];

// ---------------------------------------------------------------------------
// Kernel A: per-batch cumsum via shuffle warp-scans, scatter frame index,
// mel_len writes. One block per batch, 512 threads (16 warps).
// ---------------------------------------------------------------------------
__global__ void lr_scan_scatter(const int* __restrict__ duration,
                                float* __restrict__ out_tail /* mel_len as f32 */)
{
    __shared__ int s_part[16];
    const int b    = blockIdx.x;
    const int t    = threadIdx.x;
    const int wid  = t >> 5;
    const int lane = t & 31;

    const int v = duration[b * T + t];

    int inc = v;
    #pragma unroll
    for (int off = 1; off < 32; off <<= 1) {
        int n = __shfl_up_sync(0xffffffffu, inc, off);
        if (lane >= off) inc += n;
    }
    if (lane == 31) s_part[wid] = inc;
    __syncthreads();

    if (wid == 0 && lane < 16) {
        int p = s_part[lane];
        #pragma unroll
        for (int off = 1; off < 16; off <<= 1) {
            int n = __shfl_up_sync(0x0000ffffu, p, off);
            if (lane >= off) p += n;
        }
        s_part[lane] = p;
    }
    __syncthreads();

    const int base  = (wid > 0) ? s_part[wid - 1] : 0;
    const int end   = base + inc;
    const int start = end - v;
    const int mel   = s_part[15];

    int* idx_b = g_idx + b * MAX_LEN;
    for (int p = start; p < end; ++p) idx_b[p] = t;   // <= 7 iters

    if (t == 0) {
        g_mel[b] = mel;
        out_tail[b] = (float)mel;
    }
}

// ---------------------------------------------------------------------------
// Kernel B: warp-per-row gather, 4 rows per warp, ONE top-level warp-uniform
// branch on mel: live warps run the branch-free 12-load batch (MLP=12),
// masked warps do pure zero stores (no loads), boundary warp (1/batch) mixes.
// rows = B*MAX_LEN = 262144; warps = 65536; blocks(256) = 8192 (exact).
// ---------------------------------------------------------------------------
__global__ void lr_gather(const float4* __restrict__ x,   // [B, T, D4]
                          float4* __restrict__ out)        // [B, MAX_LEN, D4]
{
    const int warp = (blockIdx.x * blockDim.x + threadIdx.x) >> 5;
    const int lane = threadIdx.x & 31;
    const int row0 = warp * ROWS_PER_WARP;    // row = b*MAX_LEN + p
    const int b    = row0 >> 12;              // / MAX_LEN (rows of a warp share b)
    const int p0   = row0 & (MAX_LEN - 1);
    const int mel  = __ldg(&g_mel[b]);

    const float4 z = make_float4(0.f, 0.f, 0.f, 0.f);
    float4* dst0 = out + (long long)row0 * D4;
    const float4* xb = x + (long long)b * T * D4;

    if (p0 + ROWS_PER_WARP <= mel) {
        // ---- fully live: straight-line batched loads, MLP = 12 ----
        int idxr[ROWS_PER_WARP];
        #pragma unroll
        for (int r = 0; r < ROWS_PER_WARP; ++r)
            idxr[r] = __ldg(&g_idx[row0 + r]);

        float4 v[ROWS_PER_WARP][3];
        #pragma unroll
        for (int r = 0; r < ROWS_PER_WARP; ++r) {
            const float4* src = xb + (long long)idxr[r] * D4;
            v[r][0] = __ldg(src + lane);
            v[r][1] = __ldg(src + lane + 32);
            v[r][2] = __ldg(src + lane + 64);
        }
        #pragma unroll
        for (int r = 0; r < ROWS_PER_WARP; ++r) {
            float4* dst = dst0 + (long long)r * D4;
            __stcs(dst + lane,      v[r][0]);
            __stcs(dst + lane + 32, v[r][1]);
            __stcs(dst + lane + 64, v[r][2]);
        }
    } else if (p0 >= mel) {
        // ---- fully masked: pure zero stores, no loads ----
        #pragma unroll
        for (int r = 0; r < ROWS_PER_WARP; ++r) {
            float4* dst = dst0 + (long long)r * D4;
            __stcs(dst + lane,      z);
            __stcs(dst + lane + 32, z);
            __stcs(dst + lane + 64, z);
        }
    } else {
        // ---- boundary (at most 1 warp per batch) ----
        #pragma unroll
        for (int r = 0; r < ROWS_PER_WARP; ++r) {
            float4* dst = dst0 + (long long)r * D4;
            if (p0 + r < mel) {
                const int idx = __ldg(&g_idx[row0 + r]);
                const float4* src = xb + (long long)idx * D4;
                __stcs(dst + lane,      __ldg(src + lane));
                __stcs(dst + lane + 32, __ldg(src + lane + 32));
                __stcs(dst + lane + 64, __ldg(src + lane + 64));
            } else {
                __stcs(dst + lane,      z);
                __stcs(dst + lane + 32, z);
                __stcs(dst + lane + 64, z);
            }
        }
    }
}

extern "C" void kernel_launch(void* const* d_in, const int* in_sizes, int n_in,
                              void* d_out, int out_size)
{
    const float* x        = (const float*)d_in[0];
    const int*   duration = (const int*)d_in[1];

    float* out = (float*)d_out;
    float* out_tail = out + (size_t)B * MAX_LEN * D;   // mel_len region (64 floats)

    lr_scan_scatter<<<B, T>>>(duration, out_tail);

    const int total_warps = (B * MAX_LEN) / ROWS_PER_WARP;   // 65536
    const int threads = 256;
    const int blocks  = total_warps * 32 / threads;          // 8192
    lr_gather<<<blocks, threads>>>((const float4*)x, (float4*)out);
}